// round 2
// baseline (speedup 1.0000x reference)
#include <cuda_runtime.h>
#include <math.h>

// ---------------- scratch (device globals) ----------------
__device__ float g_bufA[33554432];  // 16x128x128x128
__device__ float g_bufB[16777216];  // 16x256x64x64
__device__ float g_bufC[8388608];   // 16x512x32x32
__device__ float g_bufZ[524288];    // 16x32x32x32
__device__ float g_bufQ[524288];
__device__ float g_mean[512];
__device__ float g_rstd[512];

// =============== stride-2 4x4 conv, pad 1. 64 co x 8x8 px per block ===============
__global__ __launch_bounds__(256) void conv_s2_kernel(
    const float* __restrict__ in, const float* __restrict__ w,
    const float* __restrict__ bias, float* __restrict__ out,
    int Cin, int Cout, int Hin, int Win)
{
    const int Hout = Hin >> 1, Wout = Win >> 1;
    const int tilesX = Wout >> 3;
    const int oh0 = (blockIdx.x / tilesX) << 3;
    const int ow0 = (blockIdx.x % tilesX) << 3;
    const int cob = blockIdx.y << 6;
    const int n = blockIdx.z;

    __shared__ float Wsm[64][4][17];
    __shared__ float P[4][18][21];

    const int tid = threadIdx.x;
    const int pg = tid & 15, cg = tid >> 4;
    const int row = pg >> 1;
    const int cb = (pg & 1) << 2;

    float acc[4][4];
#pragma unroll
    for (int j = 0; j < 4; ++j)
#pragma unroll
        for (int k = 0; k < 4; ++k) acc[j][k] = 0.f;

    const float* inb = in + (size_t)n * Cin * Hin * Win;

    for (int c0 = 0; c0 < Cin; c0 += 4) {
        for (int idx = tid; idx < 4096; idx += 256) {
            int co = idx >> 6, r = idx & 63, c = r >> 4, khw = r & 15;
            float v = 0.f;
            if (c0 + c < Cin)
                v = w[((size_t)(cob + co) * Cin + c0 + c) * 16 + khw];
            Wsm[co][c][khw] = v;
        }
        for (int idx = tid; idx < 4 * 324; idx += 256) {
            int c = idx / 324, r = idx - c * 324;
            int pr = r / 18, pc = r - pr * 18;
            int ih = 2 * oh0 - 1 + pr, iw = 2 * ow0 - 1 + pc;
            float v = 0.f;
            if (c0 + c < Cin && (unsigned)ih < (unsigned)Hin && (unsigned)iw < (unsigned)Win)
                v = inb[((size_t)(c0 + c) * Hin + ih) * Win + iw];
            P[c][pr][pc] = v;
        }
        __syncthreads();

#pragma unroll
        for (int c = 0; c < 4; ++c) {
#pragma unroll
            for (int kh = 0; kh < 4; ++kh) {
                const float* prow = &P[c][2 * row + kh][2 * cb];
#pragma unroll
                for (int kw = 0; kw < 4; ++kw) {
                    float a0 = prow[kw], a1 = prow[kw + 2], a2 = prow[kw + 4], a3 = prow[kw + 6];
                    int khw = (kh << 2) + kw;
                    float w0 = Wsm[(cg << 2) + 0][c][khw];
                    float w1 = Wsm[(cg << 2) + 1][c][khw];
                    float w2 = Wsm[(cg << 2) + 2][c][khw];
                    float w3 = Wsm[(cg << 2) + 3][c][khw];
                    acc[0][0] += a0 * w0; acc[0][1] += a0 * w1; acc[0][2] += a0 * w2; acc[0][3] += a0 * w3;
                    acc[1][0] += a1 * w0; acc[1][1] += a1 * w1; acc[1][2] += a1 * w2; acc[1][3] += a1 * w3;
                    acc[2][0] += a2 * w0; acc[2][1] += a2 * w1; acc[2][2] += a2 * w2; acc[2][3] += a2 * w3;
                    acc[3][0] += a3 * w0; acc[3][1] += a3 * w1; acc[3][2] += a3 * w2; acc[3][3] += a3 * w3;
                }
            }
        }
        __syncthreads();
    }

#pragma unroll
    for (int k = 0; k < 4; ++k) {
        int co = cob + (cg << 2) + k;
        float b = bias[co];
        float4 v = make_float4(acc[0][k] + b, acc[1][k] + b, acc[2][k] + b, acc[3][k] + b);
        float* op = out + (((size_t)n * Cout + co) * Hout + oh0 + row) * Wout + ow0 + cb;
        *reinterpret_cast<float4*>(op) = v;
    }
}

// =============== transposed conv k4 s2 p1 (out = 2*in). parity-selected taps ===============
__global__ __launch_bounds__(256) void convt_kernel(
    const float* __restrict__ in, const float* __restrict__ w,
    const float* __restrict__ bias, float* __restrict__ out,
    int Cin, int Cout, int Hin, int Win)
{
    const int Hout = Hin << 1, Wout = Win << 1;
    const int tilesX = Wout >> 3;
    const int oh0 = (blockIdx.x / tilesX) << 3;
    const int ow0 = (blockIdx.x % tilesX) << 3;
    const int cob = blockIdx.y << 6;
    const int n = blockIdx.z;

    __shared__ float Wsm[64][4][17];
    __shared__ float P[4][6][9];

    const int tid = threadIdx.x;
    const int pg = tid & 15, cg = tid >> 4;
    const int row = pg >> 1;
    const int cb = (pg & 1) << 2;
    const int ph = row & 1;
    const int ihl0 = (row + ph) >> 1;
    const int r0 = (oh0 >> 1) - 1;
    const int col0 = (ow0 >> 1) - 1;

    float acc[4][4];
#pragma unroll
    for (int j = 0; j < 4; ++j)
#pragma unroll
        for (int k = 0; k < 4; ++k) acc[j][k] = 0.f;

    const float* inb = in + (size_t)n * Cin * Hin * Win;

    for (int c0 = 0; c0 < Cin; c0 += 4) {
        for (int idx = tid; idx < 4096; idx += 256) {
            int co = idx >> 6, r = idx & 63, c = r >> 4, khw = r & 15;
            Wsm[co][c][khw] = w[((size_t)(cob + co) * Cin + c0 + c) * 16 + khw];
        }
        for (int idx = tid; idx < 144; idx += 256) {
            int c = idx / 36, r = idx - c * 36;
            int rr = r / 6, cc = r - rr * 6;
            int ih = r0 + rr, iw = col0 + cc;
            float v = 0.f;
            if ((unsigned)ih < (unsigned)Hin && (unsigned)iw < (unsigned)Win)
                v = inb[((size_t)(c0 + c) * Hin + ih) * Win + iw];
            P[c][rr][cc] = v;
        }
        __syncthreads();

#pragma unroll
        for (int c = 0; c < 4; ++c) {
#pragma unroll
            for (int dh = 0; dh < 2; ++dh) {
                const int kh = ph + (dh << 1);
                const float* prow = &P[c][ihl0 + dh][cb >> 1];
#pragma unroll
                for (int dw = 0; dw < 2; ++dw) {
                    float t0 = prow[dw], t1 = prow[dw + 1], t2 = prow[dw + 2];
                    int khwE = (kh << 2) + (dw << 1);
#pragma unroll
                    for (int k = 0; k < 4; ++k) {
                        float we = Wsm[(cg << 2) + k][c][khwE];
                        float wo = Wsm[(cg << 2) + k][c][khwE + 1];
                        acc[0][k] += t0 * we;
                        acc[1][k] += t1 * wo;
                        acc[2][k] += t1 * we;
                        acc[3][k] += t2 * wo;
                    }
                }
            }
        }
        __syncthreads();
    }

#pragma unroll
    for (int k = 0; k < 4; ++k) {
        int co = cob + (cg << 2) + k;
        float b = bias[co];
        float4 v = make_float4(acc[0][k] + b, acc[1][k] + b, acc[2][k] + b, acc[3][k] + b);
        float* op = out + (((size_t)n * Cout + co) * Hout + oh0 + row) * Wout + ow0 + cb;
        *reinterpret_cast<float4*>(op) = v;
    }
}

// =============== final transposed conv 128->3 + tanh ===============
__global__ __launch_bounds__(256) void convt_final_kernel(
    const float* __restrict__ in, const float* __restrict__ w,
    const float* __restrict__ bias, float* __restrict__ out)
{
    const int n = blockIdx.y;
    const int oh0 = (blockIdx.x >> 4) << 4;
    const int ow0 = (blockIdx.x & 15) << 4;
    __shared__ float P[8][10][11];
    __shared__ float Wsm[8][3][17];
    const int tid = threadIdx.x;
    const int py = tid >> 4, px = tid & 15;
    const int ph = py & 1, pw = px & 1;
    const int ihl0 = (py + ph) >> 1, iwl0 = (px + pw) >> 1;
    const int r0 = (oh0 >> 1) - 1, col0 = (ow0 >> 1) - 1;
    float acc0 = 0.f, acc1 = 0.f, acc2 = 0.f;
    const float* inb = in + ((size_t)n << 21);

    for (int c0 = 0; c0 < 128; c0 += 8) {
        for (int idx = tid; idx < 800; idx += 256) {
            int c = idx / 100, r = idx - c * 100;
            int rr = r / 10, cc = r - rr * 10;
            int ih = r0 + rr, iw = col0 + cc;
            float v = 0.f;
            if ((unsigned)ih < 128u && (unsigned)iw < 128u)
                v = inb[((size_t)(c0 + c) << 14) + (ih << 7) + iw];
            P[c][rr][cc] = v;
        }
        for (int idx = tid; idx < 384; idx += 256) {
            int c = idx / 48, r = idx - c * 48;
            int co = r >> 4, khw = r & 15;
            Wsm[c][co][khw] = w[((size_t)co * 128 + c0 + c) * 16 + khw];
        }
        __syncthreads();
#pragma unroll
        for (int c = 0; c < 8; ++c) {
#pragma unroll
            for (int dh = 0; dh < 2; ++dh) {
#pragma unroll
                for (int dw = 0; dw < 2; ++dw) {
                    float a = P[c][ihl0 + dh][iwl0 + dw];
                    int khw = ((ph + (dh << 1)) << 2) + pw + (dw << 1);
                    acc0 += a * Wsm[c][0][khw];
                    acc1 += a * Wsm[c][1][khw];
                    acc2 += a * Wsm[c][2][khw];
                }
            }
        }
        __syncthreads();
    }
    const int oh = oh0 + py, ow = ow0 + px;
    size_t base = ((size_t)n * 3) * 65536 + ((size_t)oh << 8) + ow;
    out[base]          = tanhf(acc0 + bias[0]);
    out[base + 65536]  = tanhf(acc1 + bias[1]);
    out[base + 131072] = tanhf(acc2 + bias[2]);
}

// =============== group-norm stats: one block per (n,group) contiguous span ===============
__global__ __launch_bounds__(256) void gn_stats_kernel(const float* __restrict__ x, int span)
{
    const float* p = x + (size_t)blockIdx.x * span;
    float s = 0.f, ss = 0.f;
    for (int i = threadIdx.x; i < span; i += 256) {
        float v = p[i];
        s += v; ss += v * v;
    }
#pragma unroll
    for (int o = 16; o; o >>= 1) {
        s  += __shfl_down_sync(0xffffffffu, s, o);
        ss += __shfl_down_sync(0xffffffffu, ss, o);
    }
    __shared__ float as[8], bs[8];
    int wi = threadIdx.x >> 5, l = threadIdx.x & 31;
    if (l == 0) { as[wi] = s; bs[wi] = ss; }
    __syncthreads();
    if (threadIdx.x == 0) {
        s = 0.f; ss = 0.f;
#pragma unroll
        for (int i = 0; i < 8; ++i) { s += as[i]; ss += bs[i]; }
        float m = s / (float)span;
        float var = ss / (float)span - m * m;
        g_mean[blockIdx.x] = m;
        g_rstd[blockIdx.x] = rsqrtf(var + 1e-5f);
    }
}

// =============== fused GN apply + SiLU, in place, float4 ===============
__global__ __launch_bounds__(256) void gn_apply_silu_kernel(
    float* __restrict__ x, const float* __restrict__ gamma, const float* __restrict__ beta,
    int C, int HW, int cpg)
{
    size_t i = (size_t)blockIdx.x * 256 + threadIdx.x;
    size_t e = i * 4;
    size_t ch = e / (size_t)HW;
    int c = (int)(ch % C);
    int n = (int)(ch / C);
    int gi = n * 32 + c / cpg;
    float m = g_mean[gi], r = g_rstd[gi];
    float ga = gamma[c], be = beta[c];
    float4 v = *reinterpret_cast<float4*>(x + e);
    float y;
    y = (v.x - m) * r * ga + be; v.x = y / (1.f + expf(-y));
    y = (v.y - m) * r * ga + be; v.y = y / (1.f + expf(-y));
    y = (v.z - m) * r * ga + be; v.z = y / (1.f + expf(-y));
    y = (v.w - m) * r * ga + be; v.w = y / (1.f + expf(-y));
    *reinterpret_cast<float4*>(x + e) = v;
}

// =============== 1x1 conv 512->32 ===============
__global__ __launch_bounds__(256) void conv1x1_enc3_kernel(
    const float* __restrict__ in, const float* __restrict__ w,
    const float* __restrict__ bias, float* __restrict__ out)
{
    const int t = blockIdx.x * 256 + threadIdx.x;
    const int n = t >> 10, pix = t & 1023;
    __shared__ float wsm[128][33];
    float acc[32];
#pragma unroll
    for (int k = 0; k < 32; ++k) acc[k] = 0.f;
    for (int c0 = 0; c0 < 512; c0 += 128) {
        __syncthreads();
        for (int idx = threadIdx.x; idx < 4096; idx += 256) {
            int co = idx >> 7, cc = idx & 127;
            wsm[cc][co] = w[(size_t)co * 512 + c0 + cc];
        }
        __syncthreads();
        for (int cc = 0; cc < 128; ++cc) {
            float a = in[(((size_t)n * 512 + c0 + cc) << 10) + pix];
#pragma unroll
            for (int k = 0; k < 32; ++k) acc[k] += a * wsm[cc][k];
        }
    }
#pragma unroll
    for (int k = 0; k < 32; ++k)
        out[(((size_t)n * 32 + k) << 10) + pix] = acc[k] + bias[k];
}

// =============== vector quantization: each vector is a contiguous 32-float row ===============
__global__ __launch_bounds__(256) void vq_kernel(
    const float* __restrict__ z, const float* __restrict__ cbk,
    float* __restrict__ q, float* __restrict__ outq, float* __restrict__ outidx)
{
    const int m = blockIdx.x * 256 + threadIdx.x;
    float v[32];
#pragma unroll
    for (int j = 0; j < 32; ++j) v[j] = z[(size_t)m * 32 + j];
    __shared__ float csm[128][33];
    __shared__ float c2sm[128];
    float best = 3.4e38f;
    int bi = 0;
    for (int k0 = 0; k0 < 1024; k0 += 128) {
        __syncthreads();
        for (int idx = threadIdx.x; idx < 4096; idx += 256)
            csm[idx >> 5][idx & 31] = cbk[(size_t)k0 * 32 + idx];
        __syncthreads();
        if (threadIdx.x < 128) {
            float s = 0.f;
#pragma unroll
            for (int j = 0; j < 32; ++j) { float c = csm[threadIdx.x][j]; s += c * c; }
            c2sm[threadIdx.x] = s;
        }
        __syncthreads();
        for (int k = 0; k < 128; ++k) {
            float dot = 0.f;
#pragma unroll
            for (int j = 0; j < 32; ++j) dot += v[j] * csm[k][j];
            float d = c2sm[k] - 2.f * dot;  // ||z||^2 constant: argmin-invariant
            if (d < best) { best = d; bi = k0 + k; }
        }
    }
#pragma unroll
    for (int j = 0; j < 32; ++j) {
        float qv = cbk[(size_t)bi * 32 + j];
        q[(size_t)m * 32 + j] = qv;
        outq[(size_t)m * 32 + j] = qv;
    }
    outidx[m] = (float)bi;
}

// =============== 1x1 conv 32->512 ===============
__global__ __launch_bounds__(256) void conv1x1_dec0_kernel(
    const float* __restrict__ q, const float* __restrict__ w,
    const float* __restrict__ bias, float* __restrict__ out)
{
    const int n = blockIdx.x >> 4;
    const int pix0 = (blockIdx.x & 15) << 6;
    const int cob = blockIdx.y << 6;
    __shared__ float qsm[32][64];
    __shared__ float wsm[32][65];
    const int tid = threadIdx.x;
    const int p = tid & 63, cg = tid >> 6;
    for (int idx = tid; idx < 2048; idx += 256) {
        int ci = idx >> 6, pp = idx & 63;
        qsm[ci][pp] = q[(((size_t)n * 32 + ci) << 10) + pix0 + pp];
    }
    for (int idx = tid; idx < 2048; idx += 256) {
        int co = idx >> 5, ci = idx & 31;
        wsm[ci][co] = w[((size_t)(cob + co) << 5) + ci];
    }
    __syncthreads();
    float acc[16];
#pragma unroll
    for (int k = 0; k < 16; ++k) acc[k] = 0.f;
#pragma unroll
    for (int ci = 0; ci < 32; ++ci) {
        float a = qsm[ci][p];
#pragma unroll
        for (int k = 0; k < 16; ++k)
            acc[k] += a * wsm[ci][(cg << 4) + k];
    }
#pragma unroll
    for (int k = 0; k < 16; ++k) {
        int co = cob + (cg << 4) + k;
        out[(((size_t)n * 512 + co) << 10) + pix0 + p] = acc[k] + bias[co];
    }
}

// =================================================================================
extern "C" void kernel_launch(void* const* d_in, const int* in_sizes, int n_in,
                              void* d_out, int out_size)
{
    const float* x       = (const float*)d_in[0];
    const float* enc0_w  = (const float*)d_in[1];
    const float* enc0_b  = (const float*)d_in[2];
    const float* enc0_g  = (const float*)d_in[3];
    const float* enc0_bt = (const float*)d_in[4];
    const float* enc1_w  = (const float*)d_in[5];
    const float* enc1_b  = (const float*)d_in[6];
    const float* enc1_g  = (const float*)d_in[7];
    const float* enc1_bt = (const float*)d_in[8];
    const float* enc2_w  = (const float*)d_in[9];
    const float* enc2_b  = (const float*)d_in[10];
    const float* enc2_g  = (const float*)d_in[11];
    const float* enc2_bt = (const float*)d_in[12];
    const float* enc3_w  = (const float*)d_in[13];
    const float* enc3_b  = (const float*)d_in[14];
    const float* codebook= (const float*)d_in[15];
    const float* dec0_w  = (const float*)d_in[16];
    const float* dec0_b  = (const float*)d_in[17];
    const float* dec1_w  = (const float*)d_in[18];
    const float* dec1_b  = (const float*)d_in[19];
    const float* dec1_g  = (const float*)d_in[20];
    const float* dec1_bt = (const float*)d_in[21];
    const float* dec2_w  = (const float*)d_in[22];
    const float* dec2_b  = (const float*)d_in[23];
    const float* dec2_g  = (const float*)d_in[24];
    const float* dec2_bt = (const float*)d_in[25];
    const float* dec3_w  = (const float*)d_in[26];
    const float* dec3_b  = (const float*)d_in[27];

    float* out = (float*)d_out;

    float *bufA, *bufB, *bufC, *bufZ, *bufQ;
    cudaGetSymbolAddress((void**)&bufA, g_bufA);
    cudaGetSymbolAddress((void**)&bufB, g_bufB);
    cudaGetSymbolAddress((void**)&bufC, g_bufC);
    cudaGetSymbolAddress((void**)&bufZ, g_bufZ);
    cudaGetSymbolAddress((void**)&bufQ, g_bufQ);

    // ---- encoder ----
    conv_s2_kernel<<<dim3(256, 2, 16), 256>>>(x, enc0_w, enc0_b, bufA, 3, 128, 256, 256);
    gn_stats_kernel<<<512, 256>>>(bufA, 4 * 128 * 128);
    gn_apply_silu_kernel<<<32768, 256>>>(bufA, enc0_g, enc0_bt, 128, 128 * 128, 4);

    conv_s2_kernel<<<dim3(64, 4, 16), 256>>>(bufA, enc1_w, enc1_b, bufB, 128, 256, 128, 128);
    gn_stats_kernel<<<512, 256>>>(bufB, 8 * 64 * 64);
    gn_apply_silu_kernel<<<16384, 256>>>(bufB, enc1_g, enc1_bt, 256, 64 * 64, 8);

    conv_s2_kernel<<<dim3(16, 8, 16), 256>>>(bufB, enc2_w, enc2_b, bufC, 256, 512, 64, 64);
    gn_stats_kernel<<<512, 256>>>(bufC, 16 * 32 * 32);
    gn_apply_silu_kernel<<<8192, 256>>>(bufC, enc2_g, enc2_bt, 512, 32 * 32, 16);

    conv1x1_enc3_kernel<<<64, 256>>>(bufC, enc3_w, enc3_b, bufZ);

    // ---- VQ (writes q + idx sections of output too) ----
    vq_kernel<<<64, 256>>>(bufZ, codebook, bufQ, out + 3145728, out + 3670016);

    // ---- decoder ----
    conv1x1_dec0_kernel<<<dim3(256, 8), 256>>>(bufQ, dec0_w, dec0_b, bufC);

    convt_kernel<<<dim3(64, 4, 16), 256>>>(bufC, dec1_w, dec1_b, bufB, 512, 256, 32, 32);
    gn_stats_kernel<<<512, 256>>>(bufB, 8 * 64 * 64);
    gn_apply_silu_kernel<<<16384, 256>>>(bufB, dec1_g, dec1_bt, 256, 64 * 64, 8);

    convt_kernel<<<dim3(256, 2, 16), 256>>>(bufB, dec2_w, dec2_b, bufA, 256, 128, 64, 64);
    gn_stats_kernel<<<512, 256>>>(bufA, 4 * 128 * 128);
    gn_apply_silu_kernel<<<32768, 256>>>(bufA, dec2_g, dec2_bt, 128, 128 * 128, 4);

    convt_final_kernel<<<dim3(256, 16), 256>>>(bufA, dec3_w, dec3_b, out);
}